// round 14
// baseline (speedup 1.0000x reference)
#include <cuda_runtime.h>

#define NB   128
#define ND   32
#define NP   16384
#define NCTA 296       // 2 CTAs per SM (regs<=64, smem ~99KB) -> one wave
#define THREADS 512
#define PSLOTS 64      // zero-padded pair slots per CTA (real np = 55-56)
#define PSTRIDE 33

typedef unsigned long long u64;

// ---- dynamic smem layout (bytes), row stride 512 everywhere ----
// CD : coefdup [64 k-rows x 512B]  (GEMM1 A)   ALIASED later by AC [64 n-rows x 512B]
// KC : Kcdup   [64 p-rows x 512B]  (GEMM2 A)
// XW : xx      [64 k-rows x 512B]  (GEMM1 B)   ALIASED later by W [64 p-rows x 512B]
// P0/LAM: 64 floats each. DEN: 512 floats (also reused as s_red).
#define OFF_CD   0
#define OFF_KC   32768
#define OFF_XW   65536
#define OFF_P0   98304
#define OFF_LAM  98560
#define OFF_DEN  98816
#define SMEM_TOTAL 100864

__device__ float g_partial[NCTA * NB * PSTRIDE];
__device__ unsigned int g_arrive;   // monotonic across graph replays

__device__ __forceinline__ u64 fma2(u64 a, u64 b, u64 c) {
    u64 d;
    asm("fma.rn.f32x2 %0, %1, %2, %3;" : "=l"(d) : "l"(a), "l"(b), "l"(c));
    return d;
}
__device__ __forceinline__ u64 pack2(float lo, float hi) {
    u64 d;
    asm("mov.b64 %0, {%1, %2};" : "=l"(d) : "f"(lo), "f"(hi));
    return d;
}
__device__ __forceinline__ void unpack2(u64 v, float& lo, float& hi) {
    asm("mov.b64 {%0, %1}, %2;" : "=f"(lo), "=f"(hi) : "l"(v));
}

// ---------------------------------------------------------------------------
// 296-CTA GEMM kernel, 2 CTAs/SM (32 warps/SM):
//  A) coefficients for this CTA's 64 pair-slots -> coefdup/Kcdup/p0/lam; xx.
//  B) GEMM1 logw[64p][128b]: warp = 4 p x 128 b; 3 LDS + 8 FFMA2 per k.
//     epi: w = expf(clip(logw+p0))*lam -> W (over xx).
//  C) GEMM2 AC[64n][128b]: warp = 4 rows x 128 b. den = 4 fixed 16-p chunks.
//  D) partial = x*A + C -> global; grid barrier; CTA c reduces batch c.
// All reduction orders fixed -> deterministic.
// ---------------------------------------------------------------------------
__global__ __launch_bounds__(THREADS, 2)
void gmm_all(const float* __restrict__ X,   const float* __restrict__ t_ptr,
             const float* __restrict__ Mu0, const float* __restrict__ Mu1,
             const float* __restrict__ S0,  const float* __restrict__ S1,
             const float* __restrict__ Lam, float* __restrict__ out)
{
    extern __shared__ char sm[];

    const int tid  = threadIdx.x;
    const int wid  = tid >> 5;      // 0..15
    const int lane = tid & 31;
    const int cta  = blockIdx.x;

    const int basecnt = NP / NCTA;            // 55
    const int rem     = NP - basecnt * NCTA;  // 104
    const int start   = cta * basecnt + (cta < rem ? cta : rem);
    const int np      = basecnt + (cta < rem ? 1 : 0);

    const float t     = t_ptr[0];
    const float omt   = 1.0f - t;
    const float e2    = 0.25f;
    const float e4    = 0.0625f;
    const float tt    = t * t;
    const float omt2  = omt * omt;
    const float t2omt = 2.0f * t * omt;
    const float e2tot = e2 * t * omt;

    // ---- fill xx: row d = x^2, row 32+d = x; col = batch (4B) ----
    {
        const int b  = tid & 127;
        const int dg = tid >> 7;            // 0..3 (8 dims each)
        const float* xb = X + b * ND + dg * 8;
        #pragma unroll
        for (int m = 0; m < 8; m++) {
            const int d = dg * 8 + m;
            const float v = xb[m];
            *(float*)(sm + OFF_XW + d * 512 + b * 4)        = v * v;
            *(float*)(sm + OFF_XW + (32 + d) * 512 + b * 4) = v;
        }
    }

    // ---- phase A: coefficients (warp per pair-slot, lane per dim) ----
    #pragma unroll
    for (int r = 0; r < PSLOTS / 16; r++) {
        const int sl = wid + r * 16;
        float a = 0.f, p1v = 0.f, K = 0.f, c = 0.f, p0s = 0.f, lam = 0.f;
        if (sl < np) {
            const int ij = start + sl;
            const int i  = ij >> 7;
            const int j  = ij & 127;
            lam = Lam[ij];

            const float s0 = S0[i * ND + lane];
            const float s1 = S1[j * ND + lane];
            const float Ds = sqrtf(fmaf(4.0f * s0, s1, e4));
            const float Cs = 0.5f * (Ds - e2);
            const float Sigma = omt2 * s0 + tt * s1 + t2omt * Cs + e2tot;
            const float St = (t * s1 + omt * Cs) - (omt * s0 + t * Cs) - e2 * t;

            const float mu0 = Mu0[i * ND + lane];
            const float mu1 = Mu1[j * ND + lane];
            const float mut = fmaf(t, mu1, omt * mu0);

            const float inv = __fdividef(1.0f, Sigma);
            K   = St * inv;
            a   = -0.5f * inv;
            p1v = inv * mut;
            c   = (mu1 - mu0) - K * mut;

            float p0 = fmaf(a * mut, mut, -0.5f * __logf(Sigma));
            #pragma unroll
            for (int off = 16; off; off >>= 1)
                p0 += __shfl_xor_sync(0xFFFFFFFFu, p0, off);
            p0s = p0;
        }
        // coefdup: row k (k=lane: p2, k=32+lane: p1), col = pair slot (dup u64)
        *(u64*)(sm + OFF_CD + lane * 512 + sl * 8)        = pack2(a, a);
        *(u64*)(sm + OFF_CD + (32 + lane) * 512 + sl * 8) = pack2(p1v, p1v);
        // Kcdup: row p, col n (n=lane: K, n=32+lane: c), dup u64
        *(u64*)(sm + OFF_KC + sl * 512 + lane * 8)        = pack2(K, K);
        *(u64*)(sm + OFF_KC + sl * 512 + (32 + lane) * 8) = pack2(c, c);
        if (lane == 0) {
            ((float*)(sm + OFF_P0))[sl]  = p0s;
            ((float*)(sm + OFF_LAM))[sl] = lam;
        }
    }
    __syncthreads();

    // ---- phase B: GEMM1. warp = p's wid*4..+3, all 128 b ----
    u64 acc[4][2];
    {
        const float* p0v = (const float*)(sm + OFF_P0);
        #pragma unroll
        for (int i = 0; i < 4; i++) {
            const float v = p0v[wid * 4 + i];
            acc[i][0] = acc[i][1] = pack2(v, v);
        }
        const char* xxb = sm + OFF_XW + lane * 16;   // 4 batches per lane
        const char* cdb = sm + OFF_CD + wid * 32;    // 4 dup'd p per warp
        #pragma unroll 4
        for (int k = 0; k < 64; k++) {
            const ulonglong2 bv = *(const ulonglong2*)(xxb + k * 512);
            const ulonglong2 a0 = *(const ulonglong2*)(cdb + k * 512);
            const ulonglong2 a1 = *(const ulonglong2*)(cdb + k * 512 + 16);
            acc[0][0] = fma2(a0.x, bv.x, acc[0][0]);
            acc[0][1] = fma2(a0.x, bv.y, acc[0][1]);
            acc[1][0] = fma2(a0.y, bv.x, acc[1][0]);
            acc[1][1] = fma2(a0.y, bv.y, acc[1][1]);
            acc[2][0] = fma2(a1.x, bv.x, acc[2][0]);
            acc[2][1] = fma2(a1.x, bv.y, acc[2][1]);
            acc[3][0] = fma2(a1.y, bv.x, acc[3][0]);
            acc[3][1] = fma2(a1.y, bv.y, acc[3][1]);
        }
    }
    __syncthreads();   // xx reads done everywhere; region XW becomes W

    // ---- phase B epilogue: w = exp(clip(logw)) * lam -> W[p][b] ----
    {
        const float* lamv = (const float*)(sm + OFF_LAM);
        #pragma unroll
        for (int i = 0; i < 4; i++) {
            const int p = wid * 4 + i;
            const float lam = lamv[p];
            float f0, f1, f2, f3;
            unpack2(acc[i][0], f0, f1);
            unpack2(acc[i][1], f2, f3);
            f0 = __expf(fminf(fmaxf(f0, -50.f), 50.f)) * lam;
            f1 = __expf(fminf(fmaxf(f1, -50.f), 50.f)) * lam;
            f2 = __expf(fminf(fmaxf(f2, -50.f), 50.f)) * lam;
            f3 = __expf(fminf(fmaxf(f3, -50.f), 50.f)) * lam;
            ulonglong2 wv;
            wv.x = pack2(f0, f1);
            wv.y = pack2(f2, f3);
            *(ulonglong2*)(sm + OFF_XW + p * 512 + lane * 16) = wv;
        }
    }
    __syncthreads();

    // ---- phase C: GEMM2. warp = rows wid*4..+3 of [K|c], all 128 b ----
    u64 ac[4][2];
    #pragma unroll
    for (int i = 0; i < 4; i++) ac[i][0] = ac[i][1] = 0ull;
    {
        const char* wb  = sm + OFF_XW + lane * 16;
        const char* kcb = sm + OFF_KC + wid * 32;
        #pragma unroll 4
        for (int p = 0; p < 64; p++) {
            const ulonglong2 bv = *(const ulonglong2*)(wb + p * 512);
            const ulonglong2 a0 = *(const ulonglong2*)(kcb + p * 512);
            const ulonglong2 a1 = *(const ulonglong2*)(kcb + p * 512 + 16);
            ac[0][0] = fma2(a0.x, bv.x, ac[0][0]);
            ac[0][1] = fma2(a0.x, bv.y, ac[0][1]);
            ac[1][0] = fma2(a0.y, bv.x, ac[1][0]);
            ac[1][1] = fma2(a0.y, bv.y, ac[1][1]);
            ac[2][0] = fma2(a1.x, bv.x, ac[2][0]);
            ac[2][1] = fma2(a1.x, bv.y, ac[2][1]);
            ac[3][0] = fma2(a1.y, bv.x, ac[3][0]);
            ac[3][1] = fma2(a1.y, bv.y, ac[3][1]);
        }
    }
    // den: thread (b = tid>>2, qa = tid&3) sums its 16 p's (fixed order)
    {
        const int b  = tid >> 2;
        const int qa = tid & 3;
        const char* wcol = sm + OFF_XW + b * 4;
        float s = 0.f;
        #pragma unroll
        for (int p = qa * 16; p < qa * 16 + 16; p++)
            s += *(const float*)(wcol + p * 512);
        ((float*)(sm + OFF_DEN))[tid] = s;   // index = b*4 + qa == tid
    }
    __syncthreads();   // W + Kcdup + CD all dead; CD region becomes AC

    #pragma unroll
    for (int i = 0; i < 4; i++) {
        const int n = wid * 4 + i;
        ulonglong2 v;
        v.x = ac[i][0];
        v.y = ac[i][1];
        *(ulonglong2*)(sm + OFF_CD + n * 512 + lane * 16) = v;
    }
    __syncthreads();

    // ---- per-CTA partial: num[b,n] = x*A + C ; den = 4 chunks ----
    {
        const int b  = tid >> 2;
        const int nq = (tid & 3) * 8;
        float* gp = g_partial + (size_t)cta * NB * PSTRIDE + b * PSTRIDE;
        #pragma unroll
        for (int n = nq; n < nq + 8; n++) {
            const float A = *(const float*)(sm + OFF_CD + n * 512 + b * 4);
            const float C = *(const float*)(sm + OFF_CD + (32 + n) * 512 + b * 4);
            gp[n] = fmaf(X[b * ND + n], A, C);
        }
        if ((tid & 3) == 0) {
            const float* dq = (const float*)(sm + OFF_DEN) + b * 4;
            gp[32] = ((dq[0] + dq[1]) + (dq[2] + dq[3]));
        }
    }

    // ---- grid-wide arrival barrier (all 296 CTAs co-resident: 2/SM) ----
    __threadfence();
    __syncthreads();
    if (tid == 0) {
        const unsigned ticket = atomicAdd(&g_arrive, 1u);
        if (cta < NB) {
            const unsigned target = (ticket / NCTA + 1u) * NCTA;
            unsigned v;
            do {
                asm volatile("ld.acquire.gpu.global.u32 %0, [%1];"
                             : "=r"(v) : "l"(&g_arrive));
            } while (v < target);
        }
    }
    if (cta >= NB) return;
    __syncthreads();

    // ---- final reduce: CTA owns batch = cta ----
    {
        float* s_red = (float*)(sm + OFF_DEN);
        const int w2i = tid >> 5;     // 0..15
        const int ln  = tid & 31;
        const float* bp = g_partial + cta * PSTRIDE;

        float a3[3];
        const int nn[3] = {w2i, w2i + 16, 32};
        #pragma unroll
        for (int r = 0; r < 3; r++) {
            float accv = 0.f;
            #pragma unroll
            for (int i = 0; i < 10; i++) {
                const int c = ln + 32 * i;
                if (c < NCTA)
                    accv += __ldcg(bp + (size_t)c * NB * PSTRIDE + nn[r]);
            }
            #pragma unroll
            for (int off = 16; off; off >>= 1)
                accv += __shfl_xor_sync(0xFFFFFFFFu, accv, off);
            a3[r] = accv;
        }
        __syncthreads();
        if (ln == 0) {
            s_red[nn[0]] = a3[0];
            s_red[nn[1]] = a3[1];
            if (w2i == 0) s_red[32] = a3[2];
        }
    }
    __syncthreads();

    if (tid < ND) {
        const float* s_red = (const float*)(sm + OFF_DEN);
        out[cta * ND + tid] = s_red[tid] / s_red[32];
    }
}

// ---------------------------------------------------------------------------
extern "C" void kernel_launch(void* const* d_in, const int* in_sizes, int n_in,
                              void* d_out, int out_size)
{
    const float* X   = (const float*)d_in[0];
    const float* t   = (const float*)d_in[1];
    const float* Mu0 = (const float*)d_in[2];
    const float* Mu1 = (const float*)d_in[3];
    const float* S0  = (const float*)d_in[4];
    const float* S1  = (const float*)d_in[5];
    const float* Lam = (const float*)d_in[6];
    float* out = (float*)d_out;

    cudaFuncSetAttribute(gmm_all,
                         cudaFuncAttributeMaxDynamicSharedMemorySize, SMEM_TOTAL);
    gmm_all<<<NCTA, THREADS, SMEM_TOTAL>>>(X, t, Mu0, Mu1, S0, S1, Lam, out);
}

// round 15
// speedup vs baseline: 1.9662x; 1.9662x over previous
#include <cuda_runtime.h>

#define NB   128
#define ND   32
#define NP   16384
#define NCTA 148       // 1 CTA per SM, one wave -> grid barrier safe
#define THREADS 512
#define TILE 28        // pairs per tile
#define NTILES 4       // 4*28 = 112 slots >= max np (111)
#define GROUPS 4
#define PPT (TILE/GROUPS)   // 7 pairs per group per tile
#define PSTRIDE 33

typedef unsigned long long u64;

__device__ float g_partial[NCTA * NB * PSTRIDE];
__device__ unsigned int g_arrive;   // monotonic across graph replays

__device__ __forceinline__ u64 fma2(u64 a, u64 b, u64 c) {
    u64 d;
    asm("fma.rn.f32x2 %0, %1, %2, %3;" : "=l"(d) : "l"(a), "l"(b), "l"(c));
    return d;
}
__device__ __forceinline__ u64 add2(u64 a, u64 b) {
    u64 d;
    asm("add.rn.f32x2 %0, %1, %2;" : "=l"(d) : "l"(a), "l"(b));
    return d;
}
__device__ __forceinline__ u64 pack2(float lo, float hi) {
    u64 d;
    asm("mov.b64 %0, {%1, %2};" : "=l"(d) : "f"(lo), "f"(hi));
    return d;
}
__device__ __forceinline__ void unpack2(u64 v, float& lo, float& hi) {
    asm("mov.b64 {%0, %1}, %2;" : "=f"(lo), "=f"(hi) : "l"(v));
}

// per-pair coefficient math (lane = dim). valid=false -> all zeros (padding).
__device__ __forceinline__ void coeff_pair(
    int ij, bool valid, int lane,
    float t, float omt, float tt, float omt2, float t2omt, float e2tot,
    const float* __restrict__ Mu0, const float* __restrict__ Mu1,
    const float* __restrict__ S0,  const float* __restrict__ S1,
    const float* __restrict__ Lam,
    float& a, float& p1v, float& K, float& c, float& p0s, float& lam)
{
    a = 0.f; p1v = 0.f; K = 0.f; c = 0.f; p0s = 0.f; lam = 0.f;
    if (valid) {
        const float e2 = 0.25f, e4 = 0.0625f;
        const int i = ij >> 7;
        const int j = ij & 127;
        lam = Lam[ij];

        const float s0 = S0[i * ND + lane];
        const float s1 = S1[j * ND + lane];
        const float Ds = sqrtf(fmaf(4.0f * s0, s1, e4));
        const float Cs = 0.5f * (Ds - e2);
        const float Sigma = omt2 * s0 + tt * s1 + t2omt * Cs + e2tot;
        const float St = (t * s1 + omt * Cs) - (omt * s0 + t * Cs) - e2 * t;

        const float mu0 = Mu0[i * ND + lane];
        const float mu1 = Mu1[j * ND + lane];
        const float mut = fmaf(t, mu1, omt * mu0);

        const float inv = __fdividef(1.0f, Sigma);
        K   = St * inv;
        a   = -0.5f * inv;
        p1v = inv * mut;
        c   = (mu1 - mu0) - K * mut;
        p0s = fmaf(a * mut, mut, -0.5f * __logf(Sigma));
    }
    // warp sum of p0 over dims (butterfly, all lanes uniform-valid)
    #pragma unroll
    for (int off = 16; off; off >>= 1)
        p0s += __shfl_xor_sync(0xFFFFFFFFu, p0s, off);
}

// ---------------------------------------------------------------------------
// R9 quartet kernel + double-buffered, latency-hidden coefficient phase:
// each tile iteration issues next tile's coeff chains (global loads + MUFU)
// BEFORE the accumulate; their only consumer (STS) sits after it, so the
// chains resolve under the FMA stream. 4 tiles of 28 pairs, 2 smem buffers.
// All reductions fixed-order -> deterministic.
// ---------------------------------------------------------------------------
__global__ __launch_bounds__(THREADS, 1)
void gmm_all(const float* __restrict__ X,   const float* __restrict__ t_ptr,
             const float* __restrict__ Mu0, const float* __restrict__ Mu1,
             const float* __restrict__ S0,  const float* __restrict__ S1,
             const float* __restrict__ Lam, float* __restrict__ out)
{
    __shared__ __align__(16) float s_p2[2][TILE * ND];
    __shared__ __align__(16) float s_p1[2][TILE * ND];
    __shared__ __align__(16) float s_pk[2][TILE * ND];
    __shared__ __align__(16) float s_pc[2][TILE * ND];
    __shared__ float s_p0[2][TILE];
    __shared__ float s_lam[2][TILE];
    __shared__ float s_red[NB * PSTRIDE];

    const int tid  = threadIdx.x;
    const int wid  = tid >> 5;
    const int lane = tid & 31;

    const int q  = lane & 3;          // dim quarter (0..3)
    const int s  = lane >> 2;         // batch slot in warp (0..7)
    const int wb = wid & 3;           // batch block (0..3)
    const int wg = wid >> 2;          // pair group (0..3)

    const int cta     = blockIdx.x;
    const int basecnt = NP / NCTA;            // 110
    const int rem     = NP - basecnt * NCTA;  // 104
    const int start   = cta * basecnt + (cta < rem ? cta : rem);
    const int np      = basecnt + (cta < rem ? 1 : 0);   // 110 or 111

    const float t     = t_ptr[0];
    const float omt   = 1.0f - t;
    const float tt    = t * t;
    const float omt2  = omt * omt;
    const float t2omt = 2.0f * t * omt;
    const float e2tot = 0.25f * t * omt;

    // x for 4 batches x 8 dims: 16 packed f32x2
    u64 xq[4][4];
    #pragma unroll
    for (int r = 0; r < 4; r++) {
        const int br = wb * 32 + r * 8 + s;
        const ulonglong2* xg = (const ulonglong2*)(X + br * ND + q * 8);
        const ulonglong2 v0 = xg[0];
        const ulonglong2 v1 = xg[1];
        xq[r][0] = v0.x; xq[r][1] = v0.y;
        xq[r][2] = v1.x; xq[r][3] = v1.y;
    }

    float den[4] = {0.f, 0.f, 0.f, 0.f};
    u64 numq[4][4];
    #pragma unroll
    for (int r = 0; r < 4; r++)
        #pragma unroll
        for (int cc = 0; cc < 4; cc++) numq[r][cc] = 0ull;

    // ---- prologue: coefficients for tile 0 -> buffer 0 ----
    {
        float a, p1v, K, c, p0s, lam;
        const int sl0 = wid;                       // slots 0..15
        coeff_pair(start + sl0, sl0 < np, lane, t, omt, tt, omt2, t2omt, e2tot,
                   Mu0, Mu1, S0, S1, Lam, a, p1v, K, c, p0s, lam);
        s_p2[0][sl0 * ND + lane] = a;
        s_p1[0][sl0 * ND + lane] = p1v;
        s_pk[0][sl0 * ND + lane] = K;
        s_pc[0][sl0 * ND + lane] = c;
        if (lane == 0) { s_p0[0][sl0] = p0s; s_lam[0][sl0] = lam; }
        if (wid < TILE - 16) {                     // slots 16..27 (warps 0..11)
            const int sl1 = wid + 16;
            coeff_pair(start + sl1, sl1 < np, lane, t, omt, tt, omt2, t2omt, e2tot,
                       Mu0, Mu1, S0, S1, Lam, a, p1v, K, c, p0s, lam);
            s_p2[0][sl1 * ND + lane] = a;
            s_p1[0][sl1 * ND + lane] = p1v;
            s_pk[0][sl1 * ND + lane] = K;
            s_pc[0][sl1 * ND + lane] = c;
            if (lane == 0) { s_p0[0][sl1] = p0s; s_lam[0][sl1] = lam; }
        }
    }
    __syncthreads();

    // ---- tile loop ----
    #pragma unroll 1
    for (int ti = 0; ti < NTILES; ti++) {
        const int cb = ti & 1;
        const int nb = cb ^ 1;

        // 1) issue next tile's coefficient chains (consumed only at step 3)
        float a0 = 0.f, b0 = 0.f, k0 = 0.f, c0 = 0.f, e0 = 0.f, l0 = 0.f;
        float a1 = 0.f, b1 = 0.f, k1 = 0.f, c1 = 0.f, e1 = 0.f, l1 = 0.f;
        const bool more = (ti < NTILES - 1);
        if (more) {
            const int gsl0 = (ti + 1) * TILE + wid;
            coeff_pair(start + gsl0, gsl0 < np, lane, t, omt, tt, omt2, t2omt,
                       e2tot, Mu0, Mu1, S0, S1, Lam, a0, b0, k0, c0, e0, l0);
            if (wid < TILE - 16) {
                const int gsl1 = gsl0 + 16;
                coeff_pair(start + gsl1, gsl1 < np, lane, t, omt, tt, omt2,
                           t2omt, e2tot, Mu0, Mu1, S0, S1, Lam,
                           a1, b1, k1, c1, e1, l1);
            }
        }

        // 2) accumulate current tile (R9 quartet inner loop)
        #pragma unroll
        for (int pp = 0; pp < PPT; pp++) {
            const int p   = wg + pp * GROUPS;
            const int off = p * ND + q * 8;

            const ulonglong2 aA = *(const ulonglong2*)(&s_p2[cb][off]);
            const ulonglong2 aB = *(const ulonglong2*)(&s_p2[cb][off + 4]);
            const ulonglong2 bA = *(const ulonglong2*)(&s_p1[cb][off]);
            const ulonglong2 bB = *(const ulonglong2*)(&s_p1[cb][off + 4]);
            const float p0  = s_p0[cb][p];
            const float lam = s_lam[cb][p];

            float w_[4];
            #pragma unroll
            for (int r = 0; r < 4; r++) {
                const u64 t0 = fma2(aA.x, xq[r][0], bA.x);
                const u64 t1 = fma2(aA.y, xq[r][1], bA.y);
                const u64 t2 = fma2(aB.x, xq[r][2], bB.x);
                const u64 t3 = fma2(aB.y, xq[r][3], bB.y);
                u64 acc0 = fma2(t0, xq[r][0], 0ull);
                u64 acc1 = fma2(t1, xq[r][1], 0ull);
                acc0 = fma2(t2, xq[r][2], acc0);
                acc1 = fma2(t3, xq[r][3], acc1);
                float lo, hi;
                unpack2(add2(acc0, acc1), lo, hi);
                float part = lo + hi;                       // this quarter
                part += __shfl_xor_sync(0xFFFFFFFFu, part, 1);
                part += __shfl_xor_sync(0xFFFFFFFFu, part, 2);
                const float logw = fminf(fmaxf(part + p0, -50.0f), 50.0f);
                w_[r] = __expf(logw) * lam;
                den[r] += w_[r];
            }

            const ulonglong2 kA = *(const ulonglong2*)(&s_pk[cb][off]);
            const ulonglong2 kB = *(const ulonglong2*)(&s_pk[cb][off + 4]);
            const ulonglong2 cA = *(const ulonglong2*)(&s_pc[cb][off]);
            const ulonglong2 cB = *(const ulonglong2*)(&s_pc[cb][off + 4]);
            #pragma unroll
            for (int r = 0; r < 4; r++) {
                const u64 w2 = pack2(w_[r], w_[r]);
                numq[r][0] = fma2(fma2(kA.x, xq[r][0], cA.x), w2, numq[r][0]);
                numq[r][1] = fma2(fma2(kA.y, xq[r][1], cA.y), w2, numq[r][1]);
                numq[r][2] = fma2(fma2(kB.x, xq[r][2], cB.x), w2, numq[r][2]);
                numq[r][3] = fma2(fma2(kB.y, xq[r][3], cB.y), w2, numq[r][3]);
            }
        }

        // 3) store next tile's coefficients to the other buffer
        if (more) {
            const int sl0 = wid;
            s_p2[nb][sl0 * ND + lane] = a0;
            s_p1[nb][sl0 * ND + lane] = b0;
            s_pk[nb][sl0 * ND + lane] = k0;
            s_pc[nb][sl0 * ND + lane] = c0;
            if (lane == 0) { s_p0[nb][sl0] = e0; s_lam[nb][sl0] = l0; }
            if (wid < TILE - 16) {
                const int sl1 = wid + 16;
                s_p2[nb][sl1 * ND + lane] = a1;
                s_p1[nb][sl1 * ND + lane] = b1;
                s_pk[nb][sl1 * ND + lane] = k1;
                s_pc[nb][sl1 * ND + lane] = c1;
                if (lane == 0) { s_p0[nb][sl1] = e1; s_lam[nb][sl1] = l1; }
            }
        }
        __syncthreads();
    }

    // ---- group combine: fixed order wg = 0,1,2,3 (deterministic) ----
    for (int gg = 0; gg < GROUPS; gg++) {
        if (wg == gg) {
            #pragma unroll
            for (int r = 0; r < 4; r++) {
                const int br = wb * 32 + r * 8 + s;
                float* my = s_red + br * PSTRIDE + q * 8;
                float f[8];
                unpack2(numq[r][0], f[0], f[1]);
                unpack2(numq[r][1], f[2], f[3]);
                unpack2(numq[r][2], f[4], f[5]);
                unpack2(numq[r][3], f[6], f[7]);
                if (gg == 0) {
                    #pragma unroll
                    for (int k = 0; k < 8; k++) my[k] = f[k];
                    if (q == 0) s_red[br * PSTRIDE + 32] = den[r];
                } else {
                    #pragma unroll
                    for (int k = 0; k < 8; k++) my[k] += f[k];
                    if (q == 0) s_red[br * PSTRIDE + 32] += den[r];
                }
            }
        }
        __syncthreads();
    }

    // write this CTA's partial to global
    {
        float* gp = g_partial + (size_t)cta * NB * PSTRIDE;
        for (int k = tid; k < NB * PSTRIDE; k += THREADS)
            gp[k] = s_red[k];
    }

    // ---- grid-wide arrival barrier (release-arrive, acquire-spin) ----
    __threadfence();
    __syncthreads();
    if (tid == 0) {
        const unsigned ticket = atomicAdd(&g_arrive, 1u);
        if (cta < NB) {
            const unsigned target = (ticket / NCTA + 1u) * NCTA;
            unsigned v;
            do {
                asm volatile("ld.acquire.gpu.global.u32 %0, [%1];"
                             : "=r"(v) : "l"(&g_arrive));
            } while (v < target);
        }
    }
    if (cta >= NB) return;       // non-reducing CTAs exit after arriving
    __syncthreads();

    // ---- final reduce: this CTA owns batch = cta ----
    {
        const int w2i = tid >> 5;
        const int ln  = tid & 31;
        const float* bp = g_partial + cta * PSTRIDE;

        float a3[3];
        const int nn[3] = {w2i & 15, (w2i & 15) + 16, 32};
        float accv[3] = {0.f, 0.f, 0.f};
        #pragma unroll
        for (int r = 0; r < 3; r++) {
            #pragma unroll
            for (int i = 0; i < 5; i++) {
                const int c = ln + 32 * i;
                if (c < NCTA)
                    accv[r] += __ldcg(bp + (size_t)c * NB * PSTRIDE + nn[r]);
            }
        }
        #pragma unroll
        for (int r = 0; r < 3; r++) {
            #pragma unroll
            for (int off = 16; off; off >>= 1)
                accv[r] += __shfl_xor_sync(0xFFFFFFFFu, accv[r], off);
            a3[r] = accv[r];
        }
        __syncthreads();   // s_red reuse: all prior readers done
        if (ln == 0 && w2i < 16) {
            s_red[nn[0]] = a3[0];
            s_red[nn[1]] = a3[1];
            if (w2i == 0) s_red[32] = a3[2];
        }
    }
    __syncthreads();

    if (tid < ND)
        out[cta * ND + tid] = s_red[tid] / s_red[32];
}

// ---------------------------------------------------------------------------
extern "C" void kernel_launch(void* const* d_in, const int* in_sizes, int n_in,
                              void* d_out, int out_size)
{
    const float* X   = (const float*)d_in[0];
    const float* t   = (const float*)d_in[1];
    const float* Mu0 = (const float*)d_in[2];
    const float* Mu1 = (const float*)d_in[3];
    const float* S0  = (const float*)d_in[4];
    const float* S1  = (const float*)d_in[5];
    const float* Lam = (const float*)d_in[6];
    float* out = (float*)d_out;

    gmm_all<<<NCTA, THREADS>>>(X, t, Mu0, Mu1, S0, S1, Lam, out);
}